// round 7
// baseline (speedup 1.0000x reference)
#include <cuda_runtime.h>
#include <cstdint>

// Dilution 2x: x [8,3,512,512] f32 -> out [8,3,1024,1024] f32
// out[b,c,2y,2x] = x[b,c,y,x]; all other outputs 0.
//
// R6 (kept): cache-policy split -- data-row stores evict_last (pinned in L2
// across graph replays), zero-row stores evict_first (streamed). Wall 24.6->21.7.
// R7: L1tex was the top resource (58.9%) because data-row stores were strided
// (64B lane stride = 16 lines/instr). Reassign so EVERY store instruction is
// contiguous: instruction s writes output chunks s*32+t (1KB/warp = 8 lines).
// Output chunk i needs input cols 4i..4i+3 -> one contiguous v4 load.
//
// Per thread, data row: 4 independent ld.v4 (batched), then 4 st.v8.
// Per thread, zero row: 4 contiguous st.v8 of zeros, no loads.

static constexpr int HF = 512, WF = 512;
static constexpr int HT = 1024, WT = 1024;
static constexpr int PLANES = 8 * 3;
static constexpr int TOTAL_THREADS = PLANES * HT * 32; // one warp per row
static constexpr int BLOCK = 256;

__device__ __forceinline__ uint4 ldg_nc4(const uint32_t* p) {
    uint4 v;
    asm("ld.global.nc.v4.b32 {%0,%1,%2,%3}, [%4];"
        : "=r"(v.x), "=r"(v.y), "=r"(v.z), "=r"(v.w) : "l"(p));
    return v;
}

__device__ __forceinline__ void stg_el8(uint32_t* p,
                                        uint32_t a, uint32_t b, uint32_t c, uint32_t d,
                                        uint32_t e, uint32_t f, uint32_t g, uint32_t h) {
    asm volatile("st.global.L2::evict_last.v8.b32 [%0], {%1,%2,%3,%4,%5,%6,%7,%8};"
                 :: "l"(p), "r"(a), "r"(b), "r"(c), "r"(d),
                    "r"(e), "r"(f), "r"(g), "r"(h) : "memory");
}

__device__ __forceinline__ void stg_ef8_zero(uint32_t* p) {
    asm volatile("st.global.L2::evict_first.v8.b32 [%0], {%1,%1,%1,%1,%1,%1,%1,%1};"
                 :: "l"(p), "r"(0u) : "memory");
}

__global__ void __launch_bounds__(BLOCK)
dilution_kernel(const uint32_t* __restrict__ in, uint32_t* __restrict__ out) {
    unsigned idx   = blockIdx.x * BLOCK + threadIdx.x;
    unsigned t     = idx & 31u;                 // lane
    unsigned row   = (idx >> 5) & (HT - 1u);    // output row
    unsigned plane = idx >> 15;                 // b*C + c

    uint32_t* orow = out + (size_t)(plane * HT + row) * WT;  // 4B words

    if (row & 1u) {
        #pragma unroll
        for (int s = 0; s < 4; s++)
            stg_ef8_zero(orow + (s * 32 + t) * 8);
    } else {
        const uint32_t* irow = in + (size_t)(plane * HF + (row >> 1)) * WF;
        uint4 a[4];
        #pragma unroll
        for (int s = 0; s < 4; s++)             // 4 independent contiguous loads
            a[s] = ldg_nc4(irow + (s * 32 + t) * 4);
        #pragma unroll
        for (int s = 0; s < 4; s++)             // contiguous 1KB per instruction
            stg_el8(orow + (s * 32 + t) * 8,
                    a[s].x, 0u, a[s].y, 0u, a[s].z, 0u, a[s].w, 0u);
    }
}

extern "C" void kernel_launch(void* const* d_in, const int* in_sizes, int n_in,
                              void* d_out, int out_size) {
    (void)in_sizes; (void)n_in; (void)out_size;
    const uint32_t* x = (const uint32_t*)d_in[0];
    uint32_t* out = (uint32_t*)d_out;
    dilution_kernel<<<TOTAL_THREADS / BLOCK, BLOCK>>>(x, out);
}

// round 8
// speedup vs baseline: 1.0087x; 1.0087x over previous
#include <cuda_runtime.h>
#include <cstdint>

// Dilution 2x: x [8,3,512,512] f32 -> out [8,3,1024,1024] f32
// out[b,c,2y,2x] = x[b,c,y,x]; all other outputs 0.
//
// Established: kernel is at the practical LTS (L2) throughput ceiling
// (~10 TB/s delivered). Remaining lever is cross-replay L2 residency:
//   - input (25MB)           : pin (evict_last)  -> DRAM fill only on 1st replay
//   - data rows (50MB stores): pin (evict_last)  -> re-dirtied in place, no WB
//   - zero rows (50MB stores): stream (evict_first) -> only steady DRAM traffic
// Resident set 75MB < L2 (~126MB) so pinning holds (R5 showed 125MB thrashes).
// sm_100 ptxas rejects L2::evict_* modifiers on <256-bit ops, so we use the
// createpolicy + L2::cache_hint form, which takes any access size.
//
// Layout (R7, best ncu dur): one warp per output row; every ld/st instruction
// is warp-contiguous. Store instr s covers output chunks s*32+t (1KB/warp);
// output chunk i needs input cols 4i..4i+3 = one contiguous v4 load.

static constexpr int HF = 512, WF = 512;
static constexpr int HT = 1024, WT = 1024;
static constexpr int PLANES = 8 * 3;
static constexpr int TOTAL_THREADS = PLANES * HT * 32; // one warp per row
static constexpr int BLOCK = 256;

__device__ __forceinline__ uint64_t policy_evict_last() {
    uint64_t p;
    asm("createpolicy.fractional.L2::evict_last.b64 %0, 1.0;" : "=l"(p));
    return p;
}

__device__ __forceinline__ uint64_t policy_evict_first() {
    uint64_t p;
    asm("createpolicy.fractional.L2::evict_first.b64 %0, 1.0;" : "=l"(p));
    return p;
}

__device__ __forceinline__ uint4 ldg_nc4_hint(const uint32_t* p, uint64_t pol) {
    uint4 v;
    asm("ld.global.nc.L2::cache_hint.v4.b32 {%0,%1,%2,%3}, [%4], %5;"
        : "=r"(v.x), "=r"(v.y), "=r"(v.z), "=r"(v.w) : "l"(p), "l"(pol));
    return v;
}

__device__ __forceinline__ void stg8_hint(uint32_t* p, uint64_t pol,
                                          uint32_t a, uint32_t b, uint32_t c, uint32_t d,
                                          uint32_t e, uint32_t f, uint32_t g, uint32_t h) {
    asm volatile("st.global.L2::cache_hint.v8.b32 [%0], {%2,%3,%4,%5,%6,%7,%8,%9}, %1;"
                 :: "l"(p), "l"(pol), "r"(a), "r"(b), "r"(c), "r"(d),
                    "r"(e), "r"(f), "r"(g), "r"(h) : "memory");
}

__global__ void __launch_bounds__(BLOCK)
dilution_kernel(const uint32_t* __restrict__ in, uint32_t* __restrict__ out) {
    unsigned idx   = blockIdx.x * BLOCK + threadIdx.x;
    unsigned t     = idx & 31u;                 // lane
    unsigned row   = (idx >> 5) & (HT - 1u);    // output row
    unsigned plane = idx >> 15;                 // b*C + c

    uint32_t* orow = out + (size_t)(plane * HT + row) * WT;  // 4B words

    if (row & 1u) {
        const uint64_t pf = policy_evict_first();
        #pragma unroll
        for (int s = 0; s < 4; s++)
            stg8_hint(orow + (s * 32 + t) * 8, pf, 0u, 0u, 0u, 0u, 0u, 0u, 0u, 0u);
    } else {
        const uint64_t pl = policy_evict_last();
        const uint32_t* irow = in + (size_t)(plane * HF + (row >> 1)) * WF;
        uint4 a[4];
        #pragma unroll
        for (int s = 0; s < 4; s++)             // 4 independent contiguous loads
            a[s] = ldg_nc4_hint(irow + (s * 32 + t) * 4, pl);
        #pragma unroll
        for (int s = 0; s < 4; s++)             // contiguous 1KB per instruction
            stg8_hint(orow + (s * 32 + t) * 8, pl,
                      a[s].x, 0u, a[s].y, 0u, a[s].z, 0u, a[s].w, 0u);
    }
}

extern "C" void kernel_launch(void* const* d_in, const int* in_sizes, int n_in,
                              void* d_out, int out_size) {
    (void)in_sizes; (void)n_in; (void)out_size;
    const uint32_t* x = (const uint32_t*)d_in[0];
    uint32_t* out = (uint32_t*)d_out;
    dilution_kernel<<<TOTAL_THREADS / BLOCK, BLOCK>>>(x, out);
}